// round 5
// baseline (speedup 1.0000x reference)
#include <cuda_runtime.h>
#include <math_constants.h>

#define FULLMASK 0xffffffffu

// ---------------- problem constants: D=64, DY=64, K=32, TAU=1 ----------------
constexpr int TPB   = 512;
constexpr int WPB   = 16;                 // warps per block
constexpr int B1    = 444;                // 3 blocks/SM * 148 SMs, one wave
constexpr int TOTW  = B1 * WPB;           // 7104 warps
constexpr int RPI   = 8;                  // rows per warp per iter
constexpr int SWEEP = TOTW * RPI;         // 56832 rows per sweep
constexpr int C1    = B1 * 32;            // 14208 candidates
constexpr int SLICE = C1 / WPB;           // 888 candidates per warp in final select

// ---------------- scratch ----------------
__device__ float        g_cd1[C1];
__device__ int          g_ci1[C1];
__device__ float        g_bsum[B1];
__device__ unsigned int g_ctr = 0;

// Select the 32 smallest of (sd[0..n), si[0..n)); executed by ONE warp.
// Marks selected slots +inf. Deterministic (value, then index tiebreak).
// sd/si may point to shared OR global memory.
__device__ __forceinline__ void warp_select_32(volatile float* sd, const int* si, int n,
                                               float* gD, int* gI) {
    int lane = threadIdx.x & 31;
    for (int k = 0; k < 32; k++) {
        float mv = CUDART_INF_F;
        int   mi = 0;
        for (int j = lane; j < n; j += 32) {
            float v = sd[j];
            if (v < mv) { mv = v; mi = j; }
        }
#pragma unroll
        for (int o = 16; o; o >>= 1) {
            float ov = __shfl_xor_sync(FULLMASK, mv, o);
            int   oi = __shfl_xor_sync(FULLMASK, mi, o);
            if (ov < mv || (ov == mv && oi < mi)) { mv = ov; mi = oi; }
        }
        if (lane == 0) {
            gD[k] = mv;
            gI[k] = si[mi];
            sd[mi] = CUDART_INF_F;
        }
        __syncwarp();
    }
}

__device__ __forceinline__ float dsq8(float4 a, float4 b, float4 qa, float4 qb) {
    float t, s0 = 0.f, s1 = 0.f;
    t = a.x - qa.x; s0 = fmaf(t, t, s0);
    t = a.y - qa.y; s1 = fmaf(t, t, s1);
    t = a.z - qa.z; s0 = fmaf(t, t, s0);
    t = a.w - qa.w; s1 = fmaf(t, t, s1);
    t = b.x - qb.x; s0 = fmaf(t, t, s0);
    t = b.y - qb.y; s1 = fmaf(t, t, s1);
    t = b.z - qb.z; s0 = fmaf(t, t, s0);
    t = b.w - qb.w; s1 = fmaf(t, t, s1);
    return s0 + s1;
}

// ---------------- fused kernel ----------------
__global__ void __launch_bounds__(512, 3) knn_fused(const float4* __restrict__ X4,
                                                    const float* __restrict__ q,
                                                    const float* __restrict__ Y,
                                                    float* __restrict__ out,
                                                    int N) {
    const int tid  = threadIdx.x;
    const int lane = tid & 31;
    const int wid  = tid >> 5;
    const int j    = lane & 7;     // position within 8-lane group
    const int sub  = lane >> 3;    // group id (0..3)
    const int gw   = blockIdx.x * WPB + wid;

    const float4 qa = *reinterpret_cast<const float4*>(q + 4 * j);
    const float4 qb = *reinterpret_cast<const float4*>(q + 32 + 4 * j);
    const float4 z4 = make_float4(0.f, 0.f, 0.f, 0.f);

    float b0 = CUDART_INF_F, b1 = CUDART_INF_F;  // per-lane top-2
    int   i0 = 0, i1 = 0;
    float acc = 0.f;

    int it = 0;
    for (int rb = gw * RPI; rb < N; rb += SWEEP, ++it) {
        const int r0 = rb + sub;
        const int r1 = rb + 4 + sub;
        const bool ok0 = r0 < N;
        const bool ok1 = r1 < N;
        const float4* p0 = X4 + (size_t)r0 * 16;
        const float4* p1 = X4 + (size_t)r1 * 16;
        float4 x0a = ok0 ? __ldg(p0 + j)     : z4;
        float4 x0b = ok0 ? __ldg(p0 + 8 + j) : z4;
        float4 x1a = ok1 ? __ldg(p1 + j)     : z4;
        float4 x1b = ok1 ? __ldg(p1 + 8 + j) : z4;

        float s0 = dsq8(x0a, x0b, qa, qb);
        float s1 = dsq8(x1a, x1b, qa, qb);
#pragma unroll
        for (int o = 1; o < 8; o <<= 1) {
            s0 += __shfl_xor_sync(FULLMASK, s0, o);
            s1 += __shfl_xor_sync(FULLMASK, s1, o);
        }
        float d0 = s0 * rsqrtf(fmaxf(s0, 1e-30f));
        float d1 = s1 * rsqrtf(fmaxf(s1, 1e-30f));
        acc += ok0 ? __expf(-d0) : 0.f;
        acc += ok1 ? __expf(-d1) : 0.f;

        const int p0h = (2 * it)     & 7;   // rotate topk duty across group lanes
        const int p1h = (2 * it + 1) & 7;
        if (ok0 && p0h == j && d0 < b1) {
            if (d0 < b0) { b1 = b0; i1 = i0; b0 = d0; i0 = r0; }
            else         { b1 = d0; i1 = r0; }
        }
        if (ok1 && p1h == j && d1 < b1) {
            if (d1 < b0) { b1 = b0; i1 = i0; b0 = d1; i0 = r1; }
            else         { b1 = d1; i1 = r1; }
        }
    }

    // ---- shared memory ----
    __shared__ float sd[2 * TPB];
    __shared__ int   si[2 * TPB];
    __shared__ float wd[WPB * 32];
    __shared__ int   wi[WPB * 32];
    __shared__ float se[WPB];
    __shared__ float fd[WPB * 32];
    __shared__ int   fi[WPB * 32];
    __shared__ float selD[32];
    __shared__ int   selI[32];
    __shared__ float selW[32];
    __shared__ float part[4][64];
    __shared__ float sredf[WPB];
    __shared__ float Ssum;
    __shared__ unsigned s_islast;

    // ---- per-block merge: 1024 candidates -> 32 ----
    sd[2 * tid]     = b0;  si[2 * tid]     = i0;
    sd[2 * tid + 1] = b1;  si[2 * tid + 1] = i1;
#pragma unroll
    for (int o = 16; o; o >>= 1) acc += __shfl_xor_sync(FULLMASK, acc, o);
    if (lane == 0) se[wid] = acc;
    __syncthreads();

    // level 1: each warp top-32 of its own 64
    warp_select_32(sd + wid * 64, si + wid * 64, 64, wd + wid * 32, wi + wid * 32);
    __syncthreads();
    // level 2: warp 0 merges 512 -> 32, writes to gmem
    if (wid == 0)
        warp_select_32(wd, wi, WPB * 32, g_cd1 + blockIdx.x * 32, g_ci1 + blockIdx.x * 32);
    if (tid == 0) {
        float s = 0.f;
#pragma unroll
        for (int i = 0; i < WPB; i++) s += se[i];
        g_bsum[blockIdx.x] = s * 0.125f;   // each row counted by its 8 group lanes
    }

    // ---- last-block handoff ----
    __syncthreads();
    __threadfence();
    if (tid == 0) s_islast = (atomicAdd(&g_ctr, 1) == B1 - 1) ? 1u : 0u;
    __syncthreads();
    if (!s_islast) return;
    __threadfence();               // acquire side: order reads after counter

    // =================== FINAL REDUCTION (last block only) ===================
    if (tid == 0) g_ctr = 0;       // reset for next graph replay

    // normalizer: deterministic sum of per-block exp sums
    float ps = 0.f;
    for (int k = tid; k < B1; k += TPB) ps += g_bsum[k];
#pragma unroll
    for (int o = 16; o; o >>= 1) ps += __shfl_xor_sync(FULLMASK, ps, o);
    if (lane == 0) sredf[wid] = ps;
    __syncthreads();
    if (tid == 0) {
        float s = 0.f;
#pragma unroll
        for (int i = 0; i < WPB; i++) s += sredf[i];
        Ssum = s;
    }

    // level 1: 16 warps, each selects top-32 of its 888-slice of the
    // (L2-resident) candidate arrays, operating directly on gmem
    warp_select_32(g_cd1 + wid * SLICE, g_ci1 + wid * SLICE, SLICE,
                   fd + wid * 32, fi + wid * 32);
    __syncthreads();
    // level 2: warp 0 merges 512 -> final 32
    if (wid == 0)
        warp_select_32(fd, fi, WPB * 32, selD, selI);
    __syncthreads();

    if (tid < 32) selW[tid] = __expf(-selD[tid]);
    __syncthreads();

    // output: 4 k-groups x 64 dims
    if (tid < 256) {
        const int dim = tid & 63;
        const int kg  = tid >> 6;
        float a = 0.f;
#pragma unroll
        for (int k = kg * 8; k < kg * 8 + 8; k++)
            a += selW[k] * __ldg(Y + (size_t)selI[k] * 64 + dim);
        part[kg][dim] = a;
    }
    __syncthreads();
    if (tid < 64)
        out[tid] = (part[0][tid] + part[1][tid] + part[2][tid] + part[3][tid]) / Ssum;
}

// ---------------- launch ----------------
extern "C" void kernel_launch(void* const* d_in, const int* in_sizes, int n_in,
                              void* d_out, int out_size) {
    const float* X = (const float*)d_in[0];   // X_train [N, 64]
    const float* Y = (const float*)d_in[1];   // y_train [N, 64]
    const float* q = (const float*)d_in[2];   // X_missing [64]
    int N = in_sizes[0] / 64;

    knn_fused<<<B1, TPB>>>((const float4*)X, q, Y, (float*)d_out, N);
}